// round 2
// baseline (speedup 1.0000x reference)
#include <cuda_runtime.h>
#include <math.h>

// Problem constants
#define B_   2
#define S_   1024
#define D_   1024
#define H_   16
#define DH_  64
#define BS_  (B_ * S_)            // 2048 rows
#define NELEM (BS_ * D_)          // 2,097,152
#define ATTN_ELEMS (B_ * H_ * S_ * S_)  // 33,554,432

// ---------------------------------------------------------------------------
// Device scratch (no cudaMalloc allowed)
// ---------------------------------------------------------------------------
__device__ float g_q[NELEM];
__device__ float g_k[NELEM];
__device__ float g_v[NELEM];
__device__ float g_av[NELEM];
__device__ float g_t0[NELEM];
__device__ float g_x1[NELEM];
__device__ float g_ffh[NELEM];
__device__ float g_out_scratch[NELEM];
__device__ float g_attn_scratch[ATTN_ELEMS];

// ---------------------------------------------------------------------------
// GEMM (NT): C[M,N] = A[M,K] * W[N,K]^T  (+bias)(+resid)(relu)
// M=2048, N=1024, K=1024. 128x128 tile, BK=8, 256 threads, 8x8 microtile.
// Double-buffered smem pipeline: 1 barrier per k-slice, loads overlap FFMAs.
// ---------------------------------------------------------------------------
__global__ __launch_bounds__(256) void gemm_nt(
    const float* __restrict__ A, const float* __restrict__ W,
    const float* __restrict__ bias, const float* __restrict__ resid,
    float* __restrict__ C, int relu)
{
    const int K = 1024, N = 1024;
    __shared__ float As[2][8][132];   // [buf][k][row]
    __shared__ float Bs[2][8][132];   // [buf][k][col]

    int tid  = threadIdx.x;
    int lrow = tid >> 1;           // 0..127
    int lcol = (tid & 1) * 4;      // 0 or 4
    int tx   = tid & 15;
    int ty   = tid >> 4;

    const float* Ap = A + ((size_t)blockIdx.y * 128 + lrow) * K + lcol;
    const float* Wp = W + ((size_t)blockIdx.x * 128 + lrow) * K + lcol;

    float acc[8][8];
#pragma unroll
    for (int i = 0; i < 8; i++)
#pragma unroll
        for (int j = 0; j < 8; j++) acc[i][j] = 0.f;

    // Prologue: load slice 0 into buffer 0
    {
        float4 a4 = *(const float4*)(Ap);
        float4 b4 = *(const float4*)(Wp);
        As[0][lcol + 0][lrow] = a4.x; As[0][lcol + 1][lrow] = a4.y;
        As[0][lcol + 2][lrow] = a4.z; As[0][lcol + 3][lrow] = a4.w;
        Bs[0][lcol + 0][lrow] = b4.x; Bs[0][lcol + 1][lrow] = b4.y;
        Bs[0][lcol + 2][lrow] = b4.z; Bs[0][lcol + 3][lrow] = b4.w;
    }
    __syncthreads();

    int buf = 0;
    for (int k0 = 0; k0 < K; k0 += 8) {
        float4 a4n, b4n;
        bool more = (k0 + 8) < K;
        if (more) {
            a4n = *(const float4*)(Ap + k0 + 8);
            b4n = *(const float4*)(Wp + k0 + 8);
        }
#pragma unroll
        for (int kk = 0; kk < 8; kk++) {
            float a[8], b[8];
            *(float4*)&a[0] = *(const float4*)&As[buf][kk][ty * 8];
            *(float4*)&a[4] = *(const float4*)&As[buf][kk][ty * 8 + 4];
            *(float4*)&b[0] = *(const float4*)&Bs[buf][kk][tx * 4];
            *(float4*)&b[4] = *(const float4*)&Bs[buf][kk][64 + tx * 4];
#pragma unroll
            for (int i = 0; i < 8; i++)
#pragma unroll
                for (int j = 0; j < 8; j++)
                    acc[i][j] += a[i] * b[j];
        }
        if (more) {
            int nb = buf ^ 1;
            As[nb][lcol + 0][lrow] = a4n.x; As[nb][lcol + 1][lrow] = a4n.y;
            As[nb][lcol + 2][lrow] = a4n.z; As[nb][lcol + 3][lrow] = a4n.w;
            Bs[nb][lcol + 0][lrow] = b4n.x; Bs[nb][lcol + 1][lrow] = b4n.y;
            Bs[nb][lcol + 2][lrow] = b4n.z; Bs[nb][lcol + 3][lrow] = b4n.w;
            __syncthreads();
            buf = nb;
        }
    }

    int row0 = blockIdx.y * 128 + ty * 8;
    int col0 = blockIdx.x * 128 + tx * 4;
    int col1 = col0 + 64;

    float4 bi0 = make_float4(0.f, 0.f, 0.f, 0.f);
    float4 bi1 = bi0;
    if (bias) {
        bi0 = *(const float4*)(bias + col0);
        bi1 = *(const float4*)(bias + col1);
    }

#pragma unroll
    for (int i = 0; i < 8; i++) {
        int row = row0 + i;
        float4 v0 = make_float4(acc[i][0] + bi0.x, acc[i][1] + bi0.y,
                                acc[i][2] + bi0.z, acc[i][3] + bi0.w);
        float4 v1 = make_float4(acc[i][4] + bi1.x, acc[i][5] + bi1.y,
                                acc[i][6] + bi1.z, acc[i][7] + bi1.w);
        if (resid) {
            float4 r0 = *(const float4*)(resid + (size_t)row * N + col0);
            float4 r1 = *(const float4*)(resid + (size_t)row * N + col1);
            v0.x += r0.x; v0.y += r0.y; v0.z += r0.z; v0.w += r0.w;
            v1.x += r1.x; v1.y += r1.y; v1.z += r1.z; v1.w += r1.w;
        }
        if (relu) {
            v0.x = fmaxf(v0.x, 0.f); v0.y = fmaxf(v0.y, 0.f);
            v0.z = fmaxf(v0.z, 0.f); v0.w = fmaxf(v0.w, 0.f);
            v1.x = fmaxf(v1.x, 0.f); v1.y = fmaxf(v1.y, 0.f);
            v1.z = fmaxf(v1.z, 0.f); v1.w = fmaxf(v1.w, 0.f);
        }
        *(float4*)(C + (size_t)row * N + col0) = v0;
        *(float4*)(C + (size_t)row * N + col1) = v1;
    }
}

// ---------------------------------------------------------------------------
// Scores: attn_raw[b,h,q,k] = (pad[b,k] ? -1e12 : q.k) * 0.125
// 64x64 tile per block over Dh=64. grid (16 ktile, 16 qtile, 32 bh)
// ---------------------------------------------------------------------------
__global__ __launch_bounds__(256) void scores_kernel(
    const float* __restrict__ q, const float* __restrict__ k,
    const int* __restrict__ mask, float* __restrict__ attn)
{
    int bh = blockIdx.z, b = bh >> 4, h = bh & 15;
    __shared__ float Qs[64][68];   // [qrow][dh]
    __shared__ float Kt[64][68];   // [dh][kcol]
    int tid = threadIdx.x;

    const float* qb = q + ((size_t)(b * S_ + blockIdx.y * 64)) * D_ + h * DH_;
    const float* kb = k + ((size_t)(b * S_ + blockIdx.x * 64)) * D_ + h * DH_;

#pragma unroll
    for (int e = 0; e < 4; e++) {
        int lin = tid + e * 256;
        {
            int row = lin >> 4, c4 = (lin & 15) * 4;
            *(float4*)&Qs[row][c4] = *(const float4*)(qb + (size_t)row * D_ + c4);
        }
        {
            int kc  = (lin & 15) | ((lin >> 8) << 4);
            int dh4 = ((lin >> 4) & 15) * 4;
            float4 b4 = *(const float4*)(kb + (size_t)kc * D_ + dh4);
            Kt[dh4 + 0][kc] = b4.x; Kt[dh4 + 1][kc] = b4.y;
            Kt[dh4 + 2][kc] = b4.z; Kt[dh4 + 3][kc] = b4.w;
        }
    }
    __syncthreads();

    int tx = tid & 15, ty = tid >> 4;
    float acc[4][4];
#pragma unroll
    for (int i = 0; i < 4; i++)
#pragma unroll
        for (int j = 0; j < 4; j++) acc[i][j] = 0.f;

#pragma unroll 8
    for (int kk = 0; kk < 64; kk++) {
        float a0 = Qs[ty * 4 + 0][kk];
        float a1 = Qs[ty * 4 + 1][kk];
        float a2 = Qs[ty * 4 + 2][kk];
        float a3 = Qs[ty * 4 + 3][kk];
        float4 bb = *(const float4*)&Kt[kk][tx * 4];
        acc[0][0] += a0 * bb.x; acc[0][1] += a0 * bb.y; acc[0][2] += a0 * bb.z; acc[0][3] += a0 * bb.w;
        acc[1][0] += a1 * bb.x; acc[1][1] += a1 * bb.y; acc[1][2] += a1 * bb.z; acc[1][3] += a1 * bb.w;
        acc[2][0] += a2 * bb.x; acc[2][1] += a2 * bb.y; acc[2][2] += a2 * bb.z; acc[2][3] += a2 * bb.w;
        acc[3][0] += a3 * bb.x; acc[3][1] += a3 * bb.y; acc[3][2] += a3 * bb.z; acc[3][3] += a3 * bb.w;
    }

    int q0  = blockIdx.y * 64 + ty * 4;
    int kc0 = blockIdx.x * 64 + tx * 4;
    int4 m4 = *(const int4*)(mask + b * S_ + kc0);
    float* out = attn + ((size_t)bh * S_ + q0) * S_ + kc0;
#pragma unroll
    for (int i = 0; i < 4; i++) {
        float4 w;
        w.x = m4.x ? -1.25e11f : acc[i][0] * 0.125f;
        w.y = m4.y ? -1.25e11f : acc[i][1] * 0.125f;
        w.z = m4.z ? -1.25e11f : acc[i][2] * 0.125f;
        w.w = m4.w ? -1.25e11f : acc[i][3] * 0.125f;
        *(float4*)(out + (size_t)i * S_) = w;
    }
}

// ---------------------------------------------------------------------------
// Block reductions
// ---------------------------------------------------------------------------
__device__ __forceinline__ float blk_reduce_max(float v, float* red) {
#pragma unroll
    for (int o = 16; o; o >>= 1) v = fmaxf(v, __shfl_xor_sync(0xffffffffu, v, o));
    int tid = threadIdx.x;
    if ((tid & 31) == 0) red[tid >> 5] = v;
    __syncthreads();
    float r = red[0];
#pragma unroll
    for (int i = 1; i < 8; i++) r = fmaxf(r, red[i]);
    __syncthreads();
    return r;
}
__device__ __forceinline__ float blk_reduce_sum(float v, float* red) {
#pragma unroll
    for (int o = 16; o; o >>= 1) v += __shfl_xor_sync(0xffffffffu, v, o);
    int tid = threadIdx.x;
    if ((tid & 31) == 0) red[tid >> 5] = v;
    __syncthreads();
    float r = red[0];
#pragma unroll
    for (int i = 1; i < 8; i++) r += red[i];
    __syncthreads();
    return r;
}

// ---------------------------------------------------------------------------
// Row softmax, in place. One block per row of 1024.
// ---------------------------------------------------------------------------
__global__ __launch_bounds__(256) void softmax_kernel(float* __restrict__ attn)
{
    __shared__ float red[8];
    size_t row = blockIdx.x;
    float* p = attn + row * (size_t)S_;
    int tid = threadIdx.x;

    float4 v = *(const float4*)(p + tid * 4);
    float m = fmaxf(fmaxf(v.x, v.y), fmaxf(v.z, v.w));
    m = blk_reduce_max(m, red);

    v.x = expf(v.x - m); v.y = expf(v.y - m);
    v.z = expf(v.z - m); v.w = expf(v.w - m);
    float s = v.x + v.y + v.z + v.w;
    s = blk_reduce_sum(s, red);

    float inv = 1.f / s;
    v.x *= inv; v.y *= inv; v.z *= inv; v.w *= inv;
    *(float4*)(p + tid * 4) = v;
}

// ---------------------------------------------------------------------------
// AV: av[b,q,h,d] = sum_k attn[b,h,q,k] * v[b,k,h,d]
// 64q x 64d per block, grid (1, 16 qtile, 32 bh)
// ---------------------------------------------------------------------------
__global__ __launch_bounds__(256) void av_kernel(
    const float* __restrict__ attn, const float* __restrict__ v,
    float* __restrict__ av)
{
    int bh = blockIdx.z, b = bh >> 4, h = bh & 15;
    __shared__ float As[64][68];   // [q][k]
    __shared__ float Vs[64][68];   // [k][d]
    int tid = threadIdx.x;
    int tx = tid & 15, ty = tid >> 4;

    const float* ab = attn + ((size_t)bh * S_ + blockIdx.y * 64) * S_;

    float acc[4][4];
#pragma unroll
    for (int i = 0; i < 4; i++)
#pragma unroll
        for (int j = 0; j < 4; j++) acc[i][j] = 0.f;

    for (int k0 = 0; k0 < S_; k0 += 64) {
#pragma unroll
        for (int e = 0; e < 4; e++) {
            int lin = tid + e * 256;
            int row = lin >> 4, c4 = (lin & 15) * 4;
            *(float4*)&As[row][c4] = *(const float4*)(ab + (size_t)row * S_ + k0 + c4);
            const float* vb = v + ((size_t)(b * S_ + k0 + row)) * D_ + h * DH_;
            *(float4*)&Vs[row][c4] = *(const float4*)(vb + c4);
        }
        __syncthreads();
#pragma unroll 8
        for (int kk = 0; kk < 64; kk++) {
            float a0 = As[ty * 4 + 0][kk];
            float a1 = As[ty * 4 + 1][kk];
            float a2 = As[ty * 4 + 2][kk];
            float a3 = As[ty * 4 + 3][kk];
            float4 bb = *(const float4*)&Vs[kk][tx * 4];
            acc[0][0] += a0 * bb.x; acc[0][1] += a0 * bb.y; acc[0][2] += a0 * bb.z; acc[0][3] += a0 * bb.w;
            acc[1][0] += a1 * bb.x; acc[1][1] += a1 * bb.y; acc[1][2] += a1 * bb.z; acc[1][3] += a1 * bb.w;
            acc[2][0] += a2 * bb.x; acc[2][1] += a2 * bb.y; acc[2][2] += a2 * bb.z; acc[2][3] += a2 * bb.w;
            acc[3][0] += a3 * bb.x; acc[3][1] += a3 * bb.y; acc[3][2] += a3 * bb.z; acc[3][3] += a3 * bb.w;
        }
        __syncthreads();
    }

    int q0 = blockIdx.y * 64 + ty * 4;
    int d0 = tx * 4;
#pragma unroll
    for (int i = 0; i < 4; i++) {
        float4 w = make_float4(acc[i][0], acc[i][1], acc[i][2], acc[i][3]);
        *(float4*)(av + ((size_t)(b * S_ + q0 + i)) * D_ + h * DH_ + d0) = w;
    }
}

// ---------------------------------------------------------------------------
// LayerNorm (ddof=1, eps added to std). One block per row of 1024.
// ---------------------------------------------------------------------------
__global__ __launch_bounds__(256) void ln_kernel(
    const float* __restrict__ in, const float* __restrict__ gamma,
    const float* __restrict__ beta, float* __restrict__ out)
{
    __shared__ float red[8];
    size_t row = blockIdx.x;
    const float* p = in + row * (size_t)D_;
    int tid = threadIdx.x;

    float4 v = *(const float4*)(p + tid * 4);
    float s = v.x + v.y + v.z + v.w;
    s = blk_reduce_sum(s, red);
    float mean = s * (1.f / (float)D_);

    float dx = v.x - mean, dy = v.y - mean, dz = v.z - mean, dw = v.w - mean;
    float ss = dx * dx + dy * dy + dz * dz + dw * dw;
    ss = blk_reduce_sum(ss, red);
    float var = ss * (1.f / (float)(D_ - 1));
    float inv = 1.f / (sqrtf(var) + 1e-8f);

    float4 g4 = *(const float4*)(gamma + tid * 4);
    float4 b4 = *(const float4*)(beta + tid * 4);
    float4 o;
    o.x = g4.x * dx * inv + b4.x;
    o.y = g4.y * dy * inv + b4.y;
    o.z = g4.z * dz * inv + b4.z;
    o.w = g4.w * dw * inv + b4.w;
    *(float4*)(out + row * (size_t)D_ + tid * 4) = o;
}

// ---------------------------------------------------------------------------
// Launch
// ---------------------------------------------------------------------------
extern "C" void kernel_launch(void* const* d_in, const int* in_sizes, int n_in,
                              void* d_out, int out_size)
{
    const float* x    = (const float*)d_in[0];
    const int*   mask = (const int*)d_in[1];
    const float* Wq   = (const float*)d_in[2];
    const float* Wk   = (const float*)d_in[3];
    const float* Wv   = (const float*)d_in[4];
    const float* Wo   = (const float*)d_in[5];
    const float* W1   = (const float*)d_in[6];
    const float* b1   = (const float*)d_in[7];
    const float* W2   = (const float*)d_in[8];
    const float* b2   = (const float*)d_in[9];
    const float* g1   = (const float*)d_in[10];
    const float* be1  = (const float*)d_in[11];
    const float* g2   = (const float*)d_in[12];
    const float* be2  = (const float*)d_in[13];
    (void)in_sizes; (void)n_in;

    float* pq; float* pk; float* pv; float* pav; float* pt0;
    float* px1; float* pffh; float* pouts; float* pattns;
    cudaGetSymbolAddress((void**)&pq,    g_q);
    cudaGetSymbolAddress((void**)&pk,    g_k);
    cudaGetSymbolAddress((void**)&pv,    g_v);
    cudaGetSymbolAddress((void**)&pav,   g_av);
    cudaGetSymbolAddress((void**)&pt0,   g_t0);
    cudaGetSymbolAddress((void**)&px1,   g_x1);
    cudaGetSymbolAddress((void**)&pffh,  g_ffh);
    cudaGetSymbolAddress((void**)&pouts, g_out_scratch);
    cudaGetSymbolAddress((void**)&pattns, g_attn_scratch);

    float* dof = (float*)d_out;
    float* out_ptr;
    float* attn_ptr;
    long long osz = (long long)out_size;
    if (osz >= (long long)NELEM + (long long)ATTN_ELEMS) {
        out_ptr = dof; attn_ptr = dof + NELEM;           // (out, attn) concatenated
    } else if (osz == (long long)ATTN_ELEMS) {
        attn_ptr = dof; out_ptr = pouts;                  // attn only
    } else if (osz == (long long)NELEM) {
        out_ptr = dof; attn_ptr = pattns;                 // out only
    } else {
        out_ptr = dof; attn_ptr = pattns;                 // defensive fallback
    }

    dim3 gemm_grid(1024 / 128, 2048 / 128);   // (8, 16)
    dim3 sc_grid(16, 16, 32);
    dim3 av_grid(1, 16, 32);

    // Q, K, V projections
    gemm_nt<<<gemm_grid, 256>>>(x, Wq, nullptr, nullptr, pq, 0);
    gemm_nt<<<gemm_grid, 256>>>(x, Wk, nullptr, nullptr, pk, 0);
    gemm_nt<<<gemm_grid, 256>>>(x, Wv, nullptr, nullptr, pv, 0);

    // Masked scaled scores -> attn region, softmax in place
    scores_kernel<<<sc_grid, 256>>>(pq, pk, mask, attn_ptr);
    softmax_kernel<<<B_ * H_ * S_, 256>>>(attn_ptr);

    // attn @ V
    av_kernel<<<av_grid, 256>>>(attn_ptr, pv, pav);

    // O-projection with fused residual (+x), then LN1
    gemm_nt<<<gemm_grid, 256>>>(pav, Wo, nullptr, x, pt0, 0);
    ln_kernel<<<BS_, 256>>>(pt0, g1, be1, px1);

    // FFN: relu(x1 W1^T + b1) W2^T + b2 + x1, then LN2 -> out
    gemm_nt<<<gemm_grid, 256>>>(px1, W1, b1, nullptr, pffh, 1);
    gemm_nt<<<gemm_grid, 256>>>(pffh, W2, b2, px1, pt0, 0);
    ln_kernel<<<BS_, 256>>>(pt0, g2, be2, out_ptr);
}

// round 4
// speedup vs baseline: 1.4173x; 1.4173x over previous
#include <cuda_runtime.h>
#include <cuda_bf16.h>
#include <stdint.h>
#include <math.h>

// Problem constants
#define B_   2
#define S_   1024
#define D_   1024
#define H_   16
#define DH_  64
#define BS_  (B_ * S_)            // 2048 rows
#define NELEM (BS_ * D_)          // 2,097,152
#define ATTN_ELEMS (B_ * H_ * S_ * S_)  // 33,554,432

// ---------------------------------------------------------------------------
// Device scratch (no cudaMalloc allowed)
// ---------------------------------------------------------------------------
__device__ float g_q[NELEM];
__device__ float g_k[NELEM];
__device__ float g_v[NELEM];
__device__ float g_av[NELEM];
__device__ float g_t0[NELEM];
__device__ float g_x1[NELEM];
__device__ float g_ffh[NELEM];
__device__ float g_out_scratch[NELEM];
__device__ float g_attn_scratch[ATTN_ELEMS];

// ---------------------------------------------------------------------------
// mma.sync helpers (legal in compute_100 PTX; no tcgen05)
// ---------------------------------------------------------------------------
__device__ __forceinline__ uint32_t smem_to_u32(const void* smem_ptr) {
    uint32_t addr;
    asm("{ .reg .u64 tmp; cvta.to.shared.u64 tmp, %1; cvt.u32.u64 %0, tmp; }"
        : "=r"(addr) : "l"(smem_ptr));
    return addr;
}

__device__ __forceinline__ void ldsm4(uint32_t addr, uint32_t* r) {
    asm volatile("ldmatrix.sync.aligned.m8n8.x4.shared.b16 {%0,%1,%2,%3}, [%4];"
        : "=r"(r[0]), "=r"(r[1]), "=r"(r[2]), "=r"(r[3]) : "r"(addr));
}

__device__ __forceinline__ void mma_bf16(float* c, const uint32_t* a, const uint32_t* b) {
    asm volatile(
        "mma.sync.aligned.m16n8k16.row.col.f32.bf16.bf16.f32 "
        "{%0,%1,%2,%3}, {%4,%5,%6,%7}, {%8,%9}, {%0,%1,%2,%3};"
        : "+f"(c[0]), "+f"(c[1]), "+f"(c[2]), "+f"(c[3])
        : "r"(a[0]), "r"(a[1]), "r"(a[2]), "r"(a[3]), "r"(b[0]), "r"(b[1]));
}

// Swizzled smem offset within one 128x32-bf16 tile (8KB).
// Physical: pairs of logical 64B rows form a 128B line of 8 16B chunks;
// chunk' = ((row&1)*4 + c) ^ ((row>>1)&7). Conflict-free for ldmatrix phases
// and for the store pattern (verified by construction).
__device__ __forceinline__ uint32_t sw_off(int row, int c) {
    return (uint32_t)(((row >> 1) << 7) |
                      ((((((row & 1) << 2) | c)) ^ ((row >> 1) & 7)) << 4));
}

// fp32x8 -> bf16 hi/lo split, packed as uint4 (8 bf16 each)
__device__ __forceinline__ void split_pack(float4 u, float4 v, uint4& hi, uint4& lo) {
    float f[8] = { u.x, u.y, u.z, u.w, v.x, v.y, v.z, v.w };
    unsigned short hs[8], ls[8];
#pragma unroll
    for (int i = 0; i < 8; i++) {
        __nv_bfloat16 hb = __float2bfloat16_rn(f[i]);
        hs[i] = __bfloat16_as_ushort(hb);
        ls[i] = __bfloat16_as_ushort(__float2bfloat16_rn(f[i] - __bfloat162float(hb)));
    }
    hi.x = (uint32_t)hs[0] | ((uint32_t)hs[1] << 16);
    hi.y = (uint32_t)hs[2] | ((uint32_t)hs[3] << 16);
    hi.z = (uint32_t)hs[4] | ((uint32_t)hs[5] << 16);
    hi.w = (uint32_t)hs[6] | ((uint32_t)hs[7] << 16);
    lo.x = (uint32_t)ls[0] | ((uint32_t)ls[1] << 16);
    lo.y = (uint32_t)ls[2] | ((uint32_t)ls[3] << 16);
    lo.z = (uint32_t)ls[4] | ((uint32_t)ls[5] << 16);
    lo.w = (uint32_t)ls[6] | ((uint32_t)ls[7] << 16);
}

// ---------------------------------------------------------------------------
// Tensor-core GEMM (NT): C[M=2048,N=1024] = A[M,K=1024] * W[N,K]^T (+bias)(+resid)(relu)
// Split bf16, 3 passes: Ahi*Whi + Ahi*Wlo + Alo*Whi, fp32 accumulation.
// BM=128, BN=128, BK=32, 256 threads (8 warps as 2x4, warp tile 64x32).
// Conversion fp32 -> (hi,lo) is done in-kernel while staging to smem.
// Smem per stage: Ahi | Alo | Whi | Wlo = 4 x 8KB; double buffered = 64KB.
// ---------------------------------------------------------------------------
#define MM_SMEM_BYTES 65536

__global__ __launch_bounds__(256) void mma_gemm(
    const float* __restrict__ A, const float* __restrict__ W,
    const float* __restrict__ bias, const float* __restrict__ resid,
    float* __restrict__ C, int relu)
{
    extern __shared__ char sm[];
    const uint32_t sbase = smem_to_u32(sm);
    const int tid  = threadIdx.x;
    const int lane = tid & 31;
    const int wid  = tid >> 5;
    const int wm   = wid >> 2;          // 0..1
    const int wn   = wid & 3;           // 0..3
    const int m0   = blockIdx.y * 128;
    const int n0   = blockIdx.x * 128;

    // ldmatrix lane->address components
    const int ra = (lane & 7) | (((lane >> 3) & 1) << 3);  // A: row-in-frag
    const int ca = lane >> 4;                              // A: k-chunk half
    const int rb = (lane & 7) | (((lane >> 4) & 1) << 3);  // B: row-in-frag
    const int cb = (lane >> 3) & 1;                        // B: k-chunk half

    float acc[4][4][4];
#pragma unroll
    for (int f = 0; f < 4; f++)
#pragma unroll
        for (int j = 0; j < 4; j++)
#pragma unroll
            for (int e = 0; e < 4; e++) acc[f][j][e] = 0.f;

    // loader task decode (4 tasks/thread; 1024 chunk-tasks: 512 A + 512 W)
    float4 pre[8];

#define GLOAD(KIDX) do { \
    const int _k0 = (KIDX) * 32; \
    _Pragma("unroll") \
    for (int _i = 0; _i < 4; _i++) { \
        int _t = tid + _i * 256; \
        int _l = _t & 511; \
        int _row = _l >> 2, _c = _l & 3; \
        const float* _src = (_t >= 512) \
            ? (W + (size_t)(n0 + _row) * 1024 + _k0 + _c * 8) \
            : (A + (size_t)(m0 + _row) * 1024 + _k0 + _c * 8); \
        pre[2 * _i]     = *(const float4*)_src; \
        pre[2 * _i + 1] = *(const float4*)(_src + 4); \
    } \
} while (0)

#define GSTORE(BUF) do { \
    _Pragma("unroll") \
    for (int _i = 0; _i < 4; _i++) { \
        int _t = tid + _i * 256; \
        int _l = _t & 511; \
        int _row = _l >> 2, _c = _l & 3; \
        uint32_t _o = sw_off(_row, _c); \
        uint32_t _tb = (uint32_t)((BUF) * 32768) + ((_t >= 512) ? 16384u : 0u); \
        uint4 _hi, _lo; \
        split_pack(pre[2 * _i], pre[2 * _i + 1], _hi, _lo); \
        *(uint4*)(sm + _tb + _o)         = _hi; \
        *(uint4*)(sm + _tb + 8192 + _o)  = _lo; \
    } \
} while (0)

    GLOAD(0);
    GSTORE(0);
    __syncthreads();

    for (int k = 0; k < 32; k++) {
        if (k < 31) GLOAD(k + 1);

        const uint32_t aB = sbase + (uint32_t)((k & 1) * 32768);
        const uint32_t wB = aB + 16384;
#pragma unroll
        for (int ks = 0; ks < 2; ks++) {
            uint32_t ah[4][4], bh[2][4], al[4][4], bl[2][4];
#pragma unroll
            for (int f = 0; f < 4; f++)
                ldsm4(aB + sw_off(wm * 64 + f * 16 + ra, 2 * ks + ca), ah[f]);
#pragma unroll
            for (int g = 0; g < 2; g++)
                ldsm4(wB + sw_off(wn * 32 + g * 16 + rb, 2 * ks + cb), bh[g]);
            // pass 1: hi*hi
#pragma unroll
            for (int f = 0; f < 4; f++)
#pragma unroll
                for (int g = 0; g < 2; g++) {
                    mma_bf16(acc[f][2 * g],     ah[f], &bh[g][0]);
                    mma_bf16(acc[f][2 * g + 1], ah[f], &bh[g][2]);
                }
            // pass 2: lo*hi
#pragma unroll
            for (int f = 0; f < 4; f++)
                ldsm4(aB + 8192 + sw_off(wm * 64 + f * 16 + ra, 2 * ks + ca), al[f]);
#pragma unroll
            for (int f = 0; f < 4; f++)
#pragma unroll
                for (int g = 0; g < 2; g++) {
                    mma_bf16(acc[f][2 * g],     al[f], &bh[g][0]);
                    mma_bf16(acc[f][2 * g + 1], al[f], &bh[g][2]);
                }
            // pass 3: hi*lo
#pragma unroll
            for (int g = 0; g < 2; g++)
                ldsm4(wB + 8192 + sw_off(wn * 32 + g * 16 + rb, 2 * ks + cb), bl[g]);
#pragma unroll
            for (int f = 0; f < 4; f++)
#pragma unroll
                for (int g = 0; g < 2; g++) {
                    mma_bf16(acc[f][2 * g],     ah[f], &bl[g][0]);
                    mma_bf16(acc[f][2 * g + 1], ah[f], &bl[g][2]);
                }
        }
        __syncthreads();
        if (k < 31) {
            GSTORE((k + 1) & 1);
            __syncthreads();
        }
    }

    // Epilogue: acc -> C with bias/resid/relu
#pragma unroll
    for (int f = 0; f < 4; f++) {
        int row = m0 + wm * 64 + f * 16 + (lane >> 2);
#pragma unroll
        for (int j = 0; j < 4; j++) {
            int col = n0 + wn * 32 + j * 8 + 2 * (lane & 3);
            float2 v0 = make_float2(acc[f][j][0], acc[f][j][1]);
            float2 v1 = make_float2(acc[f][j][2], acc[f][j][3]);
            if (bias) {
                float2 b2 = *(const float2*)(bias + col);
                v0.x += b2.x; v0.y += b2.y;
                v1.x += b2.x; v1.y += b2.y;
            }
            if (resid) {
                float2 r0 = *(const float2*)(resid + (size_t)row * 1024 + col);
                float2 r1 = *(const float2*)(resid + (size_t)(row + 8) * 1024 + col);
                v0.x += r0.x; v0.y += r0.y;
                v1.x += r1.x; v1.y += r1.y;
            }
            if (relu) {
                v0.x = fmaxf(v0.x, 0.f); v0.y = fmaxf(v0.y, 0.f);
                v1.x = fmaxf(v1.x, 0.f); v1.y = fmaxf(v1.y, 0.f);
            }
            *(float2*)(C + (size_t)row * 1024 + col)       = v0;
            *(float2*)(C + (size_t)(row + 8) * 1024 + col) = v1;
        }
    }
}

// ---------------------------------------------------------------------------
// Scores: attn_raw[b,h,q,k] = (pad[b,k] ? -1e12 : q.k) * 0.125
// ---------------------------------------------------------------------------
__global__ __launch_bounds__(256) void scores_kernel(
    const float* __restrict__ q, const float* __restrict__ k,
    const int* __restrict__ mask, float* __restrict__ attn)
{
    int bh = blockIdx.z, b = bh >> 4, h = bh & 15;
    __shared__ float Qs[64][68];
    __shared__ float Kt[64][68];
    int tid = threadIdx.x;

    const float* qb = q + ((size_t)(b * S_ + blockIdx.y * 64)) * D_ + h * DH_;
    const float* kb = k + ((size_t)(b * S_ + blockIdx.x * 64)) * D_ + h * DH_;

#pragma unroll
    for (int e = 0; e < 4; e++) {
        int lin = tid + e * 256;
        {
            int row = lin >> 4, c4 = (lin & 15) * 4;
            *(float4*)&Qs[row][c4] = *(const float4*)(qb + (size_t)row * D_ + c4);
        }
        {
            int kc  = (lin & 15) | ((lin >> 8) << 4);
            int dh4 = ((lin >> 4) & 15) * 4;
            float4 b4 = *(const float4*)(kb + (size_t)kc * D_ + dh4);
            Kt[dh4 + 0][kc] = b4.x; Kt[dh4 + 1][kc] = b4.y;
            Kt[dh4 + 2][kc] = b4.z; Kt[dh4 + 3][kc] = b4.w;
        }
    }
    __syncthreads();

    int tx = tid & 15, ty = tid >> 4;
    float acc[4][4];
#pragma unroll
    for (int i = 0; i < 4; i++)
#pragma unroll
        for (int j = 0; j < 4; j++) acc[i][j] = 0.f;

#pragma unroll 8
    for (int kk = 0; kk < 64; kk++) {
        float a0 = Qs[ty * 4 + 0][kk];
        float a1 = Qs[ty * 4 + 1][kk];
        float a2 = Qs[ty * 4 + 2][kk];
        float a3 = Qs[ty * 4 + 3][kk];
        float4 bb = *(const float4*)&Kt[kk][tx * 4];
        acc[0][0] += a0 * bb.x; acc[0][1] += a0 * bb.y; acc[0][2] += a0 * bb.z; acc[0][3] += a0 * bb.w;
        acc[1][0] += a1 * bb.x; acc[1][1] += a1 * bb.y; acc[1][2] += a1 * bb.z; acc[1][3] += a1 * bb.w;
        acc[2][0] += a2 * bb.x; acc[2][1] += a2 * bb.y; acc[2][2] += a2 * bb.z; acc[2][3] += a2 * bb.w;
        acc[3][0] += a3 * bb.x; acc[3][1] += a3 * bb.y; acc[3][2] += a3 * bb.z; acc[3][3] += a3 * bb.w;
    }

    int q0  = blockIdx.y * 64 + ty * 4;
    int kc0 = blockIdx.x * 64 + tx * 4;
    int4 m4 = *(const int4*)(mask + b * S_ + kc0);
    float* out = attn + ((size_t)bh * S_ + q0) * S_ + kc0;
#pragma unroll
    for (int i = 0; i < 4; i++) {
        float4 w;
        w.x = m4.x ? -1.25e11f : acc[i][0] * 0.125f;
        w.y = m4.y ? -1.25e11f : acc[i][1] * 0.125f;
        w.z = m4.z ? -1.25e11f : acc[i][2] * 0.125f;
        w.w = m4.w ? -1.25e11f : acc[i][3] * 0.125f;
        *(float4*)(out + (size_t)i * S_) = w;
    }
}

// ---------------------------------------------------------------------------
// Block reductions
// ---------------------------------------------------------------------------
__device__ __forceinline__ float blk_reduce_max(float v, float* red) {
#pragma unroll
    for (int o = 16; o; o >>= 1) v = fmaxf(v, __shfl_xor_sync(0xffffffffu, v, o));
    int tid = threadIdx.x;
    if ((tid & 31) == 0) red[tid >> 5] = v;
    __syncthreads();
    float r = red[0];
#pragma unroll
    for (int i = 1; i < 8; i++) r = fmaxf(r, red[i]);
    __syncthreads();
    return r;
}
__device__ __forceinline__ float blk_reduce_sum(float v, float* red) {
#pragma unroll
    for (int o = 16; o; o >>= 1) v += __shfl_xor_sync(0xffffffffu, v, o);
    int tid = threadIdx.x;
    if ((tid & 31) == 0) red[tid >> 5] = v;
    __syncthreads();
    float r = red[0];
#pragma unroll
    for (int i = 1; i < 8; i++) r += red[i];
    __syncthreads();
    return r;
}

// ---------------------------------------------------------------------------
// Row softmax, in place.
// ---------------------------------------------------------------------------
__global__ __launch_bounds__(256) void softmax_kernel(float* __restrict__ attn)
{
    __shared__ float red[8];
    size_t row = blockIdx.x;
    float* p = attn + row * (size_t)S_;
    int tid = threadIdx.x;

    float4 v = *(const float4*)(p + tid * 4);
    float m = fmaxf(fmaxf(v.x, v.y), fmaxf(v.z, v.w));
    m = blk_reduce_max(m, red);

    v.x = expf(v.x - m); v.y = expf(v.y - m);
    v.z = expf(v.z - m); v.w = expf(v.w - m);
    float s = v.x + v.y + v.z + v.w;
    s = blk_reduce_sum(s, red);

    float inv = 1.f / s;
    v.x *= inv; v.y *= inv; v.z *= inv; v.w *= inv;
    *(float4*)(p + tid * 4) = v;
}

// ---------------------------------------------------------------------------
// AV: av[b,q,h,d] = sum_k attn[b,h,q,k] * v[b,k,h,d]
// ---------------------------------------------------------------------------
__global__ __launch_bounds__(256) void av_kernel(
    const float* __restrict__ attn, const float* __restrict__ v,
    float* __restrict__ av)
{
    int bh = blockIdx.z, b = bh >> 4, h = bh & 15;
    __shared__ float As[64][68];
    __shared__ float Vs[64][68];
    int tid = threadIdx.x;
    int tx = tid & 15, ty = tid >> 4;

    const float* ab = attn + ((size_t)bh * S_ + blockIdx.y * 64) * S_;

    float acc[4][4];
#pragma unroll
    for (int i = 0; i < 4; i++)
#pragma unroll
        for (int j = 0; j < 4; j++) acc[i][j] = 0.f;

    for (int k0 = 0; k0 < S_; k0 += 64) {
#pragma unroll
        for (int e = 0; e < 4; e++) {
            int lin = tid + e * 256;
            int row = lin >> 4, c4 = (lin & 15) * 4;
            *(float4*)&As[row][c4] = *(const float4*)(ab + (size_t)row * S_ + k0 + c4);
            const float* vb = v + ((size_t)(b * S_ + k0 + row)) * D_ + h * DH_;
            *(float4*)&Vs[row][c4] = *(const float4*)(vb + c4);
        }
        __syncthreads();
#pragma unroll 8
        for (int kk = 0; kk < 64; kk++) {
            float a0 = As[ty * 4 + 0][kk];
            float a1 = As[ty * 4 + 1][kk];
            float a2 = As[ty * 4 + 2][kk];
            float a3 = As[ty * 4 + 3][kk];
            float4 bb = *(const float4*)&Vs[kk][tx * 4];
            acc[0][0] += a0 * bb.x; acc[0][1] += a0 * bb.y; acc[0][2] += a0 * bb.z; acc[0][3] += a0 * bb.w;
            acc[1][0] += a1 * bb.x; acc[1][1] += a1 * bb.y; acc[1][2] += a1 * bb.z; acc[1][3] += a1 * bb.w;
            acc[2][0] += a2 * bb.x; acc[2][1] += a2 * bb.y; acc[2][2] += a2 * bb.z; acc[2][3] += a2 * bb.w;
            acc[3][0] += a3 * bb.x; acc[3][1] += a3 * bb.y; acc[3][2] += a3 * bb.z; acc[3][3] += a3 * bb.w;
        }
        __syncthreads();
    }

    int q0 = blockIdx.y * 64 + ty * 4;
    int d0 = tx * 4;
#pragma unroll
    for (int i = 0; i < 4; i++) {
        float4 w = make_float4(acc[i][0], acc[i][1], acc[i][2], acc[i][3]);
        *(float4*)(av + ((size_t)(b * S_ + q0 + i)) * D_ + h * DH_ + d0) = w;
    }
}

// ---------------------------------------------------------------------------
// LayerNorm (ddof=1, eps added to std).
// ---------------------------------------------------------------------------
__global__ __launch_bounds__(256) void ln_kernel(
    const float* __restrict__ in, const float* __restrict__ gamma,
    const float* __restrict__ beta, float* __restrict__ out)
{
    __shared__ float red[8];
    size_t row = blockIdx.x;
    const float* p = in + row * (size_t)D_;
    int tid = threadIdx.x;

    float4 v = *(const float4*)(p + tid * 4);
    float s = v.x + v.y + v.z + v.w;
    s = blk_reduce_sum(s, red);
    float mean = s * (1.f / (float)D_);

    float dx = v.x - mean, dy = v.y - mean, dz = v.z - mean, dw = v.w - mean;
    float ss = dx * dx + dy * dy + dz * dz + dw * dw;
    ss = blk_reduce_sum(ss, red);
    float var = ss * (1.f / (float)(D_ - 1));
    float inv = 1.f / (sqrtf(var) + 1e-8f);

    float4 g4 = *(const float4*)(gamma + tid * 4);
    float4 b4 = *(const float4*)(beta + tid * 4);
    float4 o;
    o.x = g4.x * dx * inv + b4.x;
    o.y = g4.y * dy * inv + b4.y;
    o.z = g4.z * dz * inv + b4.z;
    o.w = g4.w * dw * inv + b4.w;
    *(float4*)(out + row * (size_t)D_ + tid * 4) = o;
}

// ---------------------------------------------------------------------------
// Launch
// ---------------------------------------------------------------------------
extern "C" void kernel_launch(void* const* d_in, const int* in_sizes, int n_in,
                              void* d_out, int out_size)
{
    const float* x    = (const float*)d_in[0];
    const int*   mask = (const int*)d_in[1];
    const float* Wq   = (const float*)d_in[2];
    const float* Wk   = (const float*)d_in[3];
    const float* Wv   = (const float*)d_in[4];
    const float* Wo   = (const float*)d_in[5];
    const float* W1   = (const float*)d_in[6];
    const float* b1   = (const float*)d_in[7];
    const float* W2   = (const float*)d_in[8];
    const float* b2   = (const float*)d_in[9];
    const float* g1   = (const float*)d_in[10];
    const float* be1  = (const float*)d_in[11];
    const float* g2   = (const float*)d_in[12];
    const float* be2  = (const float*)d_in[13];
    (void)in_sizes; (void)n_in;

    float *pq, *pk, *pv, *pav, *pt0, *px1, *pffh, *pouts, *pattns;
    cudaGetSymbolAddress((void**)&pq,    g_q);
    cudaGetSymbolAddress((void**)&pk,    g_k);
    cudaGetSymbolAddress((void**)&pv,    g_v);
    cudaGetSymbolAddress((void**)&pav,   g_av);
    cudaGetSymbolAddress((void**)&pt0,   g_t0);
    cudaGetSymbolAddress((void**)&px1,   g_x1);
    cudaGetSymbolAddress((void**)&pffh,  g_ffh);
    cudaGetSymbolAddress((void**)&pouts, g_out_scratch);
    cudaGetSymbolAddress((void**)&pattns, g_attn_scratch);

    cudaFuncSetAttribute(mma_gemm, cudaFuncAttributeMaxDynamicSharedMemorySize,
                         MM_SMEM_BYTES);

    float* dof = (float*)d_out;
    float* out_ptr;
    float* attn_ptr;
    long long osz = (long long)out_size;
    if (osz >= (long long)NELEM + (long long)ATTN_ELEMS) {
        out_ptr = dof; attn_ptr = dof + NELEM;
    } else if (osz == (long long)ATTN_ELEMS) {
        attn_ptr = dof; out_ptr = pouts;
    } else if (osz == (long long)NELEM) {
        out_ptr = dof; attn_ptr = pattns;
    } else {
        out_ptr = dof; attn_ptr = pattns;
    }

    dim3 mm_grid(1024 / 128, 2048 / 128);     // (8, 16)
    dim3 sc_grid(16, 16, 32);
    dim3 av_grid(1, 16, 32);

    // Q, K, V projections on tensor cores (split-bf16, conversion fused)
    mma_gemm<<<mm_grid, 256, MM_SMEM_BYTES>>>(x, Wq, nullptr, nullptr, pq, 0);
    mma_gemm<<<mm_grid, 256, MM_SMEM_BYTES>>>(x, Wk, nullptr, nullptr, pk, 0);
    mma_gemm<<<mm_grid, 256, MM_SMEM_BYTES>>>(x, Wv, nullptr, nullptr, pv, 0);

    // Masked scaled scores -> attn region, softmax in place, attn @ V
    scores_kernel<<<sc_grid, 256>>>(pq, pk, mask, attn_ptr);
    softmax_kernel<<<B_ * H_ * S_, 256>>>(attn_ptr);
    av_kernel<<<av_grid, 256>>>(attn_ptr, pv, pav);

    // O-projection with fused residual (+x), then LN1
    mma_gemm<<<mm_grid, 256, MM_SMEM_BYTES>>>(pav, Wo, nullptr, x, pt0, 0);
    ln_kernel<<<BS_, 256>>>(pt0, g1, be1, px1);

    // FFN: relu(x1 W1^T + b1) W2^T + b2 + x1, then LN2 -> out
    mma_gemm<<<mm_grid, 256, MM_SMEM_BYTES>>>(px1, W1, b1, nullptr, pffh, 1);
    mma_gemm<<<mm_grid, 256, MM_SMEM_BYTES>>>(pffh, W2, b2, px1, pt0, 0);
    ln_kernel<<<BS_, 256>>>(pt0, g2, be2, out_ptr);
}

// round 5
// speedup vs baseline: 1.4555x; 1.0270x over previous
#include <cuda_runtime.h>
#include <cuda_bf16.h>
#include <stdint.h>
#include <math.h>

// Problem constants
#define B_   2
#define S_   1024
#define D_   1024
#define H_   16
#define DH_  64
#define BS_  (B_ * S_)            // 2048 rows
#define NELEM (BS_ * D_)          // 2,097,152
#define ATTN_ELEMS (B_ * H_ * S_ * S_)  // 33,554,432

// ---------------------------------------------------------------------------
// Device scratch (no cudaMalloc allowed)
// ---------------------------------------------------------------------------
__device__ float g_q[NELEM];
__device__ float g_k[NELEM];
__device__ float g_v[NELEM];
__device__ float g_av[NELEM];
__device__ float g_t0[NELEM];
__device__ float g_x1[NELEM];
__device__ float g_ffh[NELEM];
__device__ float g_out_scratch[NELEM];
__device__ float g_attn_scratch[ATTN_ELEMS];

// ---------------------------------------------------------------------------
// mma.sync helpers (legal in compute_100 PTX; no tcgen05)
// ---------------------------------------------------------------------------
__device__ __forceinline__ uint32_t smem_to_u32(const void* smem_ptr) {
    uint32_t addr;
    asm("{ .reg .u64 tmp; cvta.to.shared.u64 tmp, %1; cvt.u32.u64 %0, tmp; }"
        : "=r"(addr) : "l"(smem_ptr));
    return addr;
}

__device__ __forceinline__ void ldsm4(uint32_t addr, uint32_t* r) {
    asm volatile("ldmatrix.sync.aligned.m8n8.x4.shared.b16 {%0,%1,%2,%3}, [%4];"
        : "=r"(r[0]), "=r"(r[1]), "=r"(r[2]), "=r"(r[3]) : "r"(addr));
}

__device__ __forceinline__ void mma_bf16(float* c, const uint32_t* a, const uint32_t* b) {
    asm volatile(
        "mma.sync.aligned.m16n8k16.row.col.f32.bf16.bf16.f32 "
        "{%0,%1,%2,%3}, {%4,%5,%6,%7}, {%8,%9}, {%0,%1,%2,%3};"
        : "+f"(c[0]), "+f"(c[1]), "+f"(c[2]), "+f"(c[3])
        : "r"(a[0]), "r"(a[1]), "r"(a[2]), "r"(a[3]), "r"(b[0]), "r"(b[1]));
}

// Swizzled smem offset within one 128x32-bf16 tile (8KB) [used by mma_gemm].
__device__ __forceinline__ uint32_t sw_off(int row, int c) {
    return (uint32_t)(((row >> 1) << 7) |
                      ((((((row & 1) << 2) | c)) ^ ((row >> 1) & 7)) << 4));
}

// Swizzled offset within a [rows][64 bf16] tile (128B rows, XOR by row&7).
__device__ __forceinline__ uint32_t sw64(int row, int ch) {
    return (uint32_t)((row << 7) | (((ch ^ (row & 7)) & 7) << 4));
}

// fp32x8 -> bf16 hi/lo split, packed as uint4 (8 bf16 each)
__device__ __forceinline__ void split_pack(float4 u, float4 v, uint4& hi, uint4& lo) {
    float f[8] = { u.x, u.y, u.z, u.w, v.x, v.y, v.z, v.w };
    unsigned short hs[8], ls[8];
#pragma unroll
    for (int i = 0; i < 8; i++) {
        __nv_bfloat16 hb = __float2bfloat16_rn(f[i]);
        hs[i] = __bfloat16_as_ushort(hb);
        ls[i] = __bfloat16_as_ushort(__float2bfloat16_rn(f[i] - __bfloat162float(hb)));
    }
    hi.x = (uint32_t)hs[0] | ((uint32_t)hs[1] << 16);
    hi.y = (uint32_t)hs[2] | ((uint32_t)hs[3] << 16);
    hi.z = (uint32_t)hs[4] | ((uint32_t)hs[5] << 16);
    hi.w = (uint32_t)hs[6] | ((uint32_t)hs[7] << 16);
    lo.x = (uint32_t)ls[0] | ((uint32_t)ls[1] << 16);
    lo.y = (uint32_t)ls[2] | ((uint32_t)ls[3] << 16);
    lo.z = (uint32_t)ls[4] | ((uint32_t)ls[5] << 16);
    lo.w = (uint32_t)ls[6] | ((uint32_t)ls[7] << 16);
}

// ---------------------------------------------------------------------------
// Tensor-core GEMM (NT): C[M=2048,N=1024] = A[M,K=1024] * W[N,K]^T (+bias)(+resid)(relu)
// Split bf16, 3 passes: Ahi*Whi + Ahi*Wlo + Alo*Whi, fp32 accumulation.
// ---------------------------------------------------------------------------
#define MM_SMEM_BYTES 65536

__global__ __launch_bounds__(256) void mma_gemm(
    const float* __restrict__ A, const float* __restrict__ W,
    const float* __restrict__ bias, const float* __restrict__ resid,
    float* __restrict__ C, int relu)
{
    extern __shared__ char sm[];
    const uint32_t sbase = smem_to_u32(sm);
    const int tid  = threadIdx.x;
    const int lane = tid & 31;
    const int wid  = tid >> 5;
    const int wm   = wid >> 2;
    const int wn   = wid & 3;
    const int m0   = blockIdx.y * 128;
    const int n0   = blockIdx.x * 128;

    const int ra = (lane & 7) | (((lane >> 3) & 1) << 3);
    const int ca = lane >> 4;
    const int rb = (lane & 7) | (((lane >> 4) & 1) << 3);
    const int cb = (lane >> 3) & 1;

    float acc[4][4][4];
#pragma unroll
    for (int f = 0; f < 4; f++)
#pragma unroll
        for (int j = 0; j < 4; j++)
#pragma unroll
            for (int e = 0; e < 4; e++) acc[f][j][e] = 0.f;

    float4 pre[8];

#define GLOAD(KIDX) do { \
    const int _k0 = (KIDX) * 32; \
    _Pragma("unroll") \
    for (int _i = 0; _i < 4; _i++) { \
        int _t = tid + _i * 256; \
        int _l = _t & 511; \
        int _row = _l >> 2, _c = _l & 3; \
        const float* _src = (_t >= 512) \
            ? (W + (size_t)(n0 + _row) * 1024 + _k0 + _c * 8) \
            : (A + (size_t)(m0 + _row) * 1024 + _k0 + _c * 8); \
        pre[2 * _i]     = *(const float4*)_src; \
        pre[2 * _i + 1] = *(const float4*)(_src + 4); \
    } \
} while (0)

#define GSTORE(BUF) do { \
    _Pragma("unroll") \
    for (int _i = 0; _i < 4; _i++) { \
        int _t = tid + _i * 256; \
        int _l = _t & 511; \
        int _row = _l >> 2, _c = _l & 3; \
        uint32_t _o = sw_off(_row, _c); \
        uint32_t _tb = (uint32_t)((BUF) * 32768) + ((_t >= 512) ? 16384u : 0u); \
        uint4 _hi, _lo; \
        split_pack(pre[2 * _i], pre[2 * _i + 1], _hi, _lo); \
        *(uint4*)(sm + _tb + _o)         = _hi; \
        *(uint4*)(sm + _tb + 8192 + _o)  = _lo; \
    } \
} while (0)

    GLOAD(0);
    GSTORE(0);
    __syncthreads();

    for (int k = 0; k < 32; k++) {
        if (k < 31) GLOAD(k + 1);

        const uint32_t aB = sbase + (uint32_t)((k & 1) * 32768);
        const uint32_t wB = aB + 16384;
#pragma unroll
        for (int ks = 0; ks < 2; ks++) {
            uint32_t ah[4][4], bh[2][4], al[4][4], bl[2][4];
#pragma unroll
            for (int f = 0; f < 4; f++)
                ldsm4(aB + sw_off(wm * 64 + f * 16 + ra, 2 * ks + ca), ah[f]);
#pragma unroll
            for (int g = 0; g < 2; g++)
                ldsm4(wB + sw_off(wn * 32 + g * 16 + rb, 2 * ks + cb), bh[g]);
#pragma unroll
            for (int f = 0; f < 4; f++)
#pragma unroll
                for (int g = 0; g < 2; g++) {
                    mma_bf16(acc[f][2 * g],     ah[f], &bh[g][0]);
                    mma_bf16(acc[f][2 * g + 1], ah[f], &bh[g][2]);
                }
#pragma unroll
            for (int f = 0; f < 4; f++)
                ldsm4(aB + 8192 + sw_off(wm * 64 + f * 16 + ra, 2 * ks + ca), al[f]);
#pragma unroll
            for (int f = 0; f < 4; f++)
#pragma unroll
                for (int g = 0; g < 2; g++) {
                    mma_bf16(acc[f][2 * g],     al[f], &bh[g][0]);
                    mma_bf16(acc[f][2 * g + 1], al[f], &bh[g][2]);
                }
#pragma unroll
            for (int g = 0; g < 2; g++)
                ldsm4(wB + 8192 + sw_off(wn * 32 + g * 16 + rb, 2 * ks + cb), bl[g]);
#pragma unroll
            for (int f = 0; f < 4; f++)
#pragma unroll
                for (int g = 0; g < 2; g++) {
                    mma_bf16(acc[f][2 * g],     ah[f], &bl[g][0]);
                    mma_bf16(acc[f][2 * g + 1], ah[f], &bl[g][2]);
                }
        }
        __syncthreads();
        if (k < 31) {
            GSTORE((k + 1) & 1);
            __syncthreads();
        }
    }

#pragma unroll
    for (int f = 0; f < 4; f++) {
        int row = m0 + wm * 64 + f * 16 + (lane >> 2);
#pragma unroll
        for (int j = 0; j < 4; j++) {
            int col = n0 + wn * 32 + j * 8 + 2 * (lane & 3);
            float2 v0 = make_float2(acc[f][j][0], acc[f][j][1]);
            float2 v1 = make_float2(acc[f][j][2], acc[f][j][3]);
            if (bias) {
                float2 b2 = *(const float2*)(bias + col);
                v0.x += b2.x; v0.y += b2.y;
                v1.x += b2.x; v1.y += b2.y;
            }
            if (resid) {
                float2 r0 = *(const float2*)(resid + (size_t)row * 1024 + col);
                float2 r1 = *(const float2*)(resid + (size_t)(row + 8) * 1024 + col);
                v0.x += r0.x; v0.y += r0.y;
                v1.x += r1.x; v1.y += r1.y;
            }
            if (relu) {
                v0.x = fmaxf(v0.x, 0.f); v0.y = fmaxf(v0.y, 0.f);
                v1.x = fmaxf(v1.x, 0.f); v1.y = fmaxf(v1.y, 0.f);
            }
            *(float2*)(C + (size_t)row * 1024 + col)       = v0;
            *(float2*)(C + (size_t)(row + 8) * 1024 + col) = v1;
        }
    }
}

// ---------------------------------------------------------------------------
// Fused scores+mask+softmax on tensor cores.
// Block: 16 q-rows x full 1024 k-positions of one (b,h).
// Grid: (64 qtiles, 32 bh). Split-bf16 QK^T (3 passes), logits live in
// accumulators, register-side softmax, single fp32 write of attn.
// smem: Qhi/lo 4KB | Kbuf x2 (hi+lo) 64KB | mask 4KB | red 1KB = 74752 B
// ---------------------------------------------------------------------------
#define FS_SMEM 74752

__global__ __launch_bounds__(256) void scores_softmax_kernel(
    const float* __restrict__ q, const float* __restrict__ k,
    const int* __restrict__ mask, float* __restrict__ attn)
{
    extern __shared__ char sm[];
    const uint32_t sbase = smem_to_u32(sm);
    const int tid = threadIdx.x;
    const int lane = tid & 31;
    const int w = tid >> 5;
    const int bh = blockIdx.y, b = bh >> 4, h = bh & 15;
    const int q0 = blockIdx.x * 16;

    int*   MS   = (int*)(sm + 69632);
    float* REDM = (float*)(sm + 73728);
    float* REDS = (float*)(sm + 74240);

    // mask -> smem
    {
        int4 mv = *(const int4*)(mask + b * 1024 + tid * 4);
        *(int4*)(MS + tid * 4) = mv;
    }
    // Q tile (16 x 64) -> split smem
    if (tid < 128) {
        int row = tid >> 3, ch = tid & 7;
        const float* src = q + ((size_t)(b * 1024 + q0 + row)) * 1024 + h * 64 + ch * 8;
        uint4 hi, lo;
        split_pack(*(const float4*)src, *(const float4*)(src + 4), hi, lo);
        uint32_t o = sw64(row, ch);
        *(uint4*)(sm + o) = hi;
        *(uint4*)(sm + 2048 + o) = lo;
    }

    float4 kr[8];
#define KFETCH(CC) do { \
    _Pragma("unroll") \
    for (int _i = 0; _i < 4; _i++) { \
        int _t = tid + _i * 256; \
        int _row = _t >> 3, _ch = _t & 7; \
        const float* _src = k + ((size_t)(b * 1024 + (CC) * 128 + _row)) * 1024 + h * 64 + _ch * 8; \
        kr[2 * _i]     = *(const float4*)_src; \
        kr[2 * _i + 1] = *(const float4*)(_src + 4); \
    } \
} while (0)

#define KSTORE(BUF) do { \
    _Pragma("unroll") \
    for (int _i = 0; _i < 4; _i++) { \
        int _t = tid + _i * 256; \
        int _row = _t >> 3, _ch = _t & 7; \
        uint4 _hi, _lo; \
        split_pack(kr[2 * _i], kr[2 * _i + 1], _hi, _lo); \
        uint32_t _o = (uint32_t)(4096 + (BUF) * 32768) + sw64(_row, _ch); \
        *(uint4*)(sm + _o)         = _hi; \
        *(uint4*)(sm + _o + 16384) = _lo; \
    } \
} while (0)

    // chunk 0
    KFETCH(0);
    KSTORE(0);
    __syncthreads();

    // A (Q) fragments: hi & lo, 4 k-steps
    const int ra = (lane & 7) | (((lane >> 3) & 1) << 3);
    const int ca = lane >> 4;
    const int rb = (lane & 7) | (((lane >> 4) & 1) << 3);
    const int cb = (lane >> 3) & 1;
    uint32_t AH[4][4], AL[4][4];
#pragma unroll
    for (int ks = 0; ks < 4; ks++) {
        uint32_t o = sw64(ra, ks * 2 + ca);
        ldsm4(sbase + o, AH[ks]);
        ldsm4(sbase + 2048 + o, AL[ks]);
    }

    float acc[8][2][4];
#pragma unroll
    for (int c = 0; c < 8; c++)
#pragma unroll
        for (int j = 0; j < 2; j++)
#pragma unroll
            for (int e = 0; e < 4; e++) acc[c][j][e] = 0.f;

    const int brow = w * 16 + rb;
    for (int c = 0; c < 8; c++) {
        if (c < 7) KFETCH(c + 1);
        const uint32_t kbu = sbase + 4096u + (uint32_t)((c & 1) * 32768);
#pragma unroll
        for (int ks = 0; ks < 4; ks++) {
            uint32_t o = sw64(brow, ks * 2 + cb);
            uint32_t BH[4], BL[4];
            ldsm4(kbu + o, BH);
            mma_bf16(acc[c][0], AH[ks], &BH[0]);
            mma_bf16(acc[c][1], AH[ks], &BH[2]);
            mma_bf16(acc[c][0], AL[ks], &BH[0]);
            mma_bf16(acc[c][1], AL[ks], &BH[2]);
            ldsm4(kbu + 16384 + o, BL);
            mma_bf16(acc[c][0], AH[ks], &BL[0]);
            mma_bf16(acc[c][1], AH[ks], &BL[2]);
        }
        if (c < 7) KSTORE((c + 1) & 1);
        __syncthreads();
    }

    // ---- mask + scale, row max ----
    const int r0 = lane >> 2;
    float mx0 = -3.0e38f, mx1 = -3.0e38f;
#pragma unroll
    for (int c = 0; c < 8; c++)
#pragma unroll
        for (int j = 0; j < 2; j++) {
            int col = c * 128 + w * 16 + j * 8 + 2 * (lane & 3);
            int mA = MS[col], mB = MS[col + 1];
            float e0 = mA ? -1.25e11f : acc[c][j][0] * 0.125f;
            float e1 = mB ? -1.25e11f : acc[c][j][1] * 0.125f;
            float e2 = mA ? -1.25e11f : acc[c][j][2] * 0.125f;
            float e3 = mB ? -1.25e11f : acc[c][j][3] * 0.125f;
            acc[c][j][0] = e0; acc[c][j][1] = e1;
            acc[c][j][2] = e2; acc[c][j][3] = e3;
            mx0 = fmaxf(mx0, fmaxf(e0, e1));
            mx1 = fmaxf(mx1, fmaxf(e2, e3));
        }
    mx0 = fmaxf(mx0, __shfl_xor_sync(0xffffffffu, mx0, 1));
    mx0 = fmaxf(mx0, __shfl_xor_sync(0xffffffffu, mx0, 2));
    mx1 = fmaxf(mx1, __shfl_xor_sync(0xffffffffu, mx1, 1));
    mx1 = fmaxf(mx1, __shfl_xor_sync(0xffffffffu, mx1, 2));
    if ((lane & 3) == 0) {
        REDM[w * 16 + r0] = mx0;
        REDM[w * 16 + r0 + 8] = mx1;
    }
    __syncthreads();
    float bm0 = -3.0e38f, bm1 = -3.0e38f;
#pragma unroll
    for (int ww = 0; ww < 8; ww++) {
        bm0 = fmaxf(bm0, REDM[ww * 16 + r0]);
        bm1 = fmaxf(bm1, REDM[ww * 16 + r0 + 8]);
    }

    // ---- exp + row sum ----
    float s0 = 0.f, s1 = 0.f;
#pragma unroll
    for (int c = 0; c < 8; c++)
#pragma unroll
        for (int j = 0; j < 2; j++) {
            float e0 = expf(acc[c][j][0] - bm0);
            float e1 = expf(acc[c][j][1] - bm0);
            float e2 = expf(acc[c][j][2] - bm1);
            float e3 = expf(acc[c][j][3] - bm1);
            acc[c][j][0] = e0; acc[c][j][1] = e1;
            acc[c][j][2] = e2; acc[c][j][3] = e3;
            s0 += e0 + e1;
            s1 += e2 + e3;
        }
    s0 += __shfl_xor_sync(0xffffffffu, s0, 1);
    s0 += __shfl_xor_sync(0xffffffffu, s0, 2);
    s1 += __shfl_xor_sync(0xffffffffu, s1, 1);
    s1 += __shfl_xor_sync(0xffffffffu, s1, 2);
    if ((lane & 3) == 0) {
        REDS[w * 16 + r0] = s0;
        REDS[w * 16 + r0 + 8] = s1;
    }
    __syncthreads();
    float t0 = 0.f, t1 = 0.f;
#pragma unroll
    for (int ww = 0; ww < 8; ww++) {
        t0 += REDS[ww * 16 + r0];
        t1 += REDS[ww * 16 + r0 + 8];
    }
    float inv0 = 1.f / t0, inv1 = 1.f / t1;

    // ---- write normalized attn (fp32) ----
    float* o0 = attn + ((size_t)bh * 1024 + q0 + r0) * 1024;
    float* o1 = o0 + 8 * 1024;
#pragma unroll
    for (int c = 0; c < 8; c++)
#pragma unroll
        for (int j = 0; j < 2; j++) {
            int col = c * 128 + w * 16 + j * 8 + 2 * (lane & 3);
            *(float2*)(o0 + col) = make_float2(acc[c][j][0] * inv0, acc[c][j][1] * inv0);
            *(float2*)(o1 + col) = make_float2(acc[c][j][2] * inv1, acc[c][j][3] * inv1);
        }
}

// ---------------------------------------------------------------------------
// Block reduction (sum)
// ---------------------------------------------------------------------------
__device__ __forceinline__ float blk_reduce_sum(float v, float* red) {
#pragma unroll
    for (int o = 16; o; o >>= 1) v += __shfl_xor_sync(0xffffffffu, v, o);
    int tid = threadIdx.x;
    if ((tid & 31) == 0) red[tid >> 5] = v;
    __syncthreads();
    float r = red[0];
#pragma unroll
    for (int i = 1; i < 8; i++) r += red[i];
    __syncthreads();
    return r;
}

// ---------------------------------------------------------------------------
// AV: av[b,q,h,d] = sum_k attn[b,h,q,k] * v[b,k,h,d]
// ---------------------------------------------------------------------------
__global__ __launch_bounds__(256) void av_kernel(
    const float* __restrict__ attn, const float* __restrict__ v,
    float* __restrict__ av)
{
    int bh = blockIdx.z, b = bh >> 4, h = bh & 15;
    __shared__ float As[64][68];
    __shared__ float Vs[64][68];
    int tid = threadIdx.x;
    int tx = tid & 15, ty = tid >> 4;

    const float* ab = attn + ((size_t)bh * S_ + blockIdx.y * 64) * S_;

    float acc[4][4];
#pragma unroll
    for (int i = 0; i < 4; i++)
#pragma unroll
        for (int j = 0; j < 4; j++) acc[i][j] = 0.f;

    for (int k0 = 0; k0 < S_; k0 += 64) {
#pragma unroll
        for (int e = 0; e < 4; e++) {
            int lin = tid + e * 256;
            int row = lin >> 4, c4 = (lin & 15) * 4;
            *(float4*)&As[row][c4] = *(const float4*)(ab + (size_t)row * S_ + k0 + c4);
            const float* vb = v + ((size_t)(b * S_ + k0 + row)) * D_ + h * DH_;
            *(float4*)&Vs[row][c4] = *(const float4*)(vb + c4);
        }
        __syncthreads();
#pragma unroll 8
        for (int kk = 0; kk < 64; kk++) {
            float a0 = As[ty * 4 + 0][kk];
            float a1 = As[ty * 4 + 1][kk];
            float a2 = As[ty * 4 + 2][kk];
            float a3 = As[ty * 4 + 3][kk];
            float4 bb = *(const float4*)&Vs[kk][tx * 4];
            acc[0][0] += a0 * bb.x; acc[0][1] += a0 * bb.y; acc[0][2] += a0 * bb.z; acc[0][3] += a0 * bb.w;
            acc[1][0] += a1 * bb.x; acc[1][1] += a1 * bb.y; acc[1][2] += a1 * bb.z; acc[1][3] += a1 * bb.w;
            acc[2][0] += a2 * bb.x; acc[2][1] += a2 * bb.y; acc[2][2] += a2 * bb.z; acc[2][3] += a2 * bb.w;
            acc[3][0] += a3 * bb.x; acc[3][1] += a3 * bb.y; acc[3][2] += a3 * bb.z; acc[3][3] += a3 * bb.w;
        }
        __syncthreads();
    }

    int q0 = blockIdx.y * 64 + ty * 4;
    int d0 = tx * 4;
#pragma unroll
    for (int i = 0; i < 4; i++) {
        float4 w = make_float4(acc[i][0], acc[i][1], acc[i][2], acc[i][3]);
        *(float4*)(av + ((size_t)(b * S_ + q0 + i)) * D_ + h * DH_ + d0) = w;
    }
}

// ---------------------------------------------------------------------------
// LayerNorm (ddof=1, eps added to std).
// ---------------------------------------------------------------------------
__global__ __launch_bounds__(256) void ln_kernel(
    const float* __restrict__ in, const float* __restrict__ gamma,
    const float* __restrict__ beta, float* __restrict__ out)
{
    __shared__ float red[8];
    size_t row = blockIdx.x;
    const float* p = in + row * (size_t)D_;
    int tid = threadIdx.x;

    float4 v = *(const float4*)(p + tid * 4);
    float s = v.x + v.y + v.z + v.w;
    s = blk_reduce_sum(s, red);
    float mean = s * (1.f / (float)D_);

    float dx = v.x - mean, dy = v.y - mean, dz = v.z - mean, dw = v.w - mean;
    float ss = dx * dx + dy * dy + dz * dz + dw * dw;
    ss = blk_reduce_sum(ss, red);
    float var = ss * (1.f / (float)(D_ - 1));
    float inv = 1.f / (sqrtf(var) + 1e-8f);

    float4 g4 = *(const float4*)(gamma + tid * 4);
    float4 b4 = *(const float4*)(beta + tid * 4);
    float4 o;
    o.x = g4.x * dx * inv + b4.x;
    o.y = g4.y * dy * inv + b4.y;
    o.z = g4.z * dz * inv + b4.z;
    o.w = g4.w * dw * inv + b4.w;
    *(float4*)(out + row * (size_t)D_ + tid * 4) = o;
}

// ---------------------------------------------------------------------------
// Launch
// ---------------------------------------------------------------------------
extern "C" void kernel_launch(void* const* d_in, const int* in_sizes, int n_in,
                              void* d_out, int out_size)
{
    const float* x    = (const float*)d_in[0];
    const int*   mask = (const int*)d_in[1];
    const float* Wq   = (const float*)d_in[2];
    const float* Wk   = (const float*)d_in[3];
    const float* Wv   = (const float*)d_in[4];
    const float* Wo   = (const float*)d_in[5];
    const float* W1   = (const float*)d_in[6];
    const float* b1   = (const float*)d_in[7];
    const float* W2   = (const float*)d_in[8];
    const float* b2   = (const float*)d_in[9];
    const float* g1   = (const float*)d_in[10];
    const float* be1  = (const float*)d_in[11];
    const float* g2   = (const float*)d_in[12];
    const float* be2  = (const float*)d_in[13];
    (void)in_sizes; (void)n_in;

    float *pq, *pk, *pv, *pav, *pt0, *px1, *pffh, *pouts, *pattns;
    cudaGetSymbolAddress((void**)&pq,    g_q);
    cudaGetSymbolAddress((void**)&pk,    g_k);
    cudaGetSymbolAddress((void**)&pv,    g_v);
    cudaGetSymbolAddress((void**)&pav,   g_av);
    cudaGetSymbolAddress((void**)&pt0,   g_t0);
    cudaGetSymbolAddress((void**)&px1,   g_x1);
    cudaGetSymbolAddress((void**)&pffh,  g_ffh);
    cudaGetSymbolAddress((void**)&pouts, g_out_scratch);
    cudaGetSymbolAddress((void**)&pattns, g_attn_scratch);

    cudaFuncSetAttribute(mma_gemm, cudaFuncAttributeMaxDynamicSharedMemorySize,
                         MM_SMEM_BYTES);
    cudaFuncSetAttribute(scores_softmax_kernel,
                         cudaFuncAttributeMaxDynamicSharedMemorySize, FS_SMEM);

    float* dof = (float*)d_out;
    float* out_ptr;
    float* attn_ptr;
    long long osz = (long long)out_size;
    if (osz >= (long long)NELEM + (long long)ATTN_ELEMS) {
        out_ptr = dof; attn_ptr = dof + NELEM;
    } else if (osz == (long long)ATTN_ELEMS) {
        attn_ptr = dof; out_ptr = pouts;
    } else if (osz == (long long)NELEM) {
        out_ptr = dof; attn_ptr = pattns;
    } else {
        out_ptr = dof; attn_ptr = pattns;
    }

    dim3 mm_grid(1024 / 128, 2048 / 128);     // (8, 16)
    dim3 fs_grid(64, 32);                     // qtiles x bh
    dim3 av_grid(1, 16, 32);

    // Q, K, V projections on tensor cores (split-bf16, conversion fused)
    mma_gemm<<<mm_grid, 256, MM_SMEM_BYTES>>>(x, Wq, nullptr, nullptr, pq, 0);
    mma_gemm<<<mm_grid, 256, MM_SMEM_BYTES>>>(x, Wk, nullptr, nullptr, pk, 0);
    mma_gemm<<<mm_grid, 256, MM_SMEM_BYTES>>>(x, Wv, nullptr, nullptr, pv, 0);

    // Fused scores + mask + softmax (tensor cores) -> attn, then attn @ V
    scores_softmax_kernel<<<fs_grid, 256, FS_SMEM>>>(pq, pk, mask, attn_ptr);
    av_kernel<<<av_grid, 256>>>(attn_ptr, pv, pav);

    // O-projection with fused residual (+x), then LN1
    mma_gemm<<<mm_grid, 256, MM_SMEM_BYTES>>>(pav, Wo, nullptr, x, pt0, 0);
    ln_kernel<<<BS_, 256>>>(pt0, g1, be1, px1);

    // FFN: relu(x1 W1^T + b1) W2^T + b2 + x1, then LN2 -> out
    mma_gemm<<<mm_grid, 256, MM_SMEM_BYTES>>>(px1, W1, b1, nullptr, pffh, 1);
    mma_gemm<<<mm_grid, 256, MM_SMEM_BYTES>>>(pffh, W2, b2, px1, pt0, 0);
    ln_kernel<<<BS_, 256>>>(pt0, g2, be2, out_ptr);
}